// round 1
// baseline (speedup 1.0000x reference)
#include <cuda_runtime.h>

#define NTHREADS 512
#define SP 513   // padded stride for xs[c][s] to kill bank conflicts

namespace {
constexpr int Bb = 2, Ss = 512, Ll = 384, CMc = 64;

struct SMem {
    float xs[64 * SP];     // post-LN x, transposed [c][s]
    float LG[8 * 512];     // logits -> attn, [h][s]
    float wgs[4096];       // wg in smem
    float wos[4096];       // wo in smem
    float maskS[512];
    float pbuf[4096];      // partial sums (reused by 2 phases)
    float trow[16 * 128];  // per-warp t = g*og buffer (2 rows)
    float qin[64];
    float qsm[64];
    float amt[512];        // a transposed [j][h]
    float ys[512];         // [h][j]
    float og[64];
    float wred[16];
    float invDenom;
};
}  // namespace

__global__ void __launch_bounds__(NTHREADS, 1)
msa_col_global_attn(const float* __restrict__ m, const float* __restrict__ msa_mask,
                    const float* __restrict__ lnw, const float* __restrict__ lnb,
                    const float* __restrict__ wq, const float* __restrict__ wk,
                    const float* __restrict__ wv, const float* __restrict__ wg,
                    const float* __restrict__ bg, const float* __restrict__ wo,
                    const float* __restrict__ bo, float* __restrict__ out)
{
    extern __shared__ char smraw[];
    SMem& sm = *reinterpret_cast<SMem*>(smraw);
    const int tid = threadIdx.x;
    const int w = tid >> 5, lane = tid & 31;
    const int b = blockIdx.x / Ll, l = blockIdx.x - b * Ll;
    const size_t rowStride = (size_t)Ll * CMc;  // stride between s for fixed (b,l)
    const float* mBase = m + ((size_t)b * Ss * Ll + l) * CMc;
    float* oBase = out + ((size_t)b * Ss * Ll + l) * CMc;

    // ---- Phase 0: mask load + denom partial, weight staging ----
    float mk = msa_mask[((size_t)b * Ss + tid) * Ll + l];
    sm.maskS[tid] = mk;
    float msum = mk;
#pragma unroll
    for (int o = 16; o; o >>= 1) msum += __shfl_xor_sync(0xffffffffu, msum, o);
    if (lane == 0) sm.wred[w] = msum;

    for (int idx = tid; idx < 2048; idx += NTHREADS) {
        reinterpret_cast<float2*>(sm.wgs)[idx] = reinterpret_cast<const float2*>(wg)[idx];
        reinterpret_cast<float2*>(sm.wos)[idx] = reinterpret_cast<const float2*>(wo)[idx];
    }
    __syncthreads();
    if (tid == 0) {
        float s = 0.f;
#pragma unroll
        for (int i = 0; i < 16; i++) s += sm.wred[i];
        sm.invDenom = 1.0f / fmaxf(s, 1.0f);
    }

    // ---- Phase 1: load m column + LayerNorm -> xs[c][s] ----
    {
        const float lw0 = lnw[2 * lane], lw1 = lnw[2 * lane + 1];
        const float lb0 = lnb[2 * lane], lb1 = lnb[2 * lane + 1];
        const float* mp = mBase + 2 * lane;
#pragma unroll 1
        for (int rb = 0; rb < 4; rb++) {
            float2 vb[8];
#pragma unroll
            for (int r = 0; r < 8; r++) {
                int s = w * 32 + rb * 8 + r;
                vb[r] = *reinterpret_cast<const float2*>(mp + (size_t)s * rowStride);
            }
#pragma unroll
            for (int r = 0; r < 8; r++) {
                int s = w * 32 + rb * 8 + r;
                float2 v = vb[r];
                float su = v.x + v.y;
                float sq = fmaf(v.x, v.x, v.y * v.y);
#pragma unroll
                for (int o = 16; o; o >>= 1) {
                    su += __shfl_xor_sync(0xffffffffu, su, o);
                    sq += __shfl_xor_sync(0xffffffffu, sq, o);
                }
                float mu = su * (1.0f / 64.0f);
                float var = sq * (1.0f / 64.0f) - mu * mu;
                float rs = rsqrtf(var + 1e-5f);
                sm.xs[(2 * lane) * SP + s]     = (v.x - mu) * rs * lw0 + lb0;
                sm.xs[(2 * lane + 1) * SP + s] = (v.y - mu) * rs * lw1 + lb1;
            }
        }
    }
    __syncthreads();

    // ---- Phase 2: masked column mean -> q_input -> q -> a[h][j] ----
    {
        int j = tid & 63, ch = tid >> 6;
        const float* xr = &sm.xs[j * SP + ch * 64];
        const float* mr = &sm.maskS[ch * 64];
        float acc = 0.f;
#pragma unroll
        for (int i = 0; i < 64; i++) acc = fmaf(xr[i], mr[i], acc);
        sm.pbuf[ch * 512 + j] = acc;
    }
    __syncthreads();
    if (tid < 64) {
        float acc = 0.f;
#pragma unroll
        for (int ch = 0; ch < 8; ch++) acc += sm.pbuf[ch * 512 + tid];
        sm.qin[tid] = acc * sm.invDenom;
    }
    __syncthreads();
    if (tid < 64) {
        float acc = 0.f;
#pragma unroll
        for (int j = 0; j < 64; j++) acc = fmaf(sm.qin[j], wq[j * 64 + tid], acc);
        sm.qsm[tid] = acc;
    }
    __syncthreads();
    {
        int h = tid >> 6, j = tid & 63;
        float acc = 0.f;
#pragma unroll
        for (int c = 0; c < 8; c++) acc = fmaf(sm.qsm[h * 8 + c], wk[j * 64 + h * 8 + c], acc);
        sm.amt[j * 8 + h] = acc * 0.35355339059327373f;  // 1/sqrt(C), C=8
    }
    __syncthreads();

    // ---- Phase 3: logits[h][s] = x[s]·a[h] , masked ----
    {
        int s = tid;
        float acc[8] = {0, 0, 0, 0, 0, 0, 0, 0};
#pragma unroll 8
        for (int j = 0; j < 64; j++) {
            float xv = sm.xs[j * SP + s];
            const float4* ap = reinterpret_cast<const float4*>(&sm.amt[j * 8]);
            float4 a0 = ap[0], a1 = ap[1];
            acc[0] = fmaf(xv, a0.x, acc[0]); acc[1] = fmaf(xv, a0.y, acc[1]);
            acc[2] = fmaf(xv, a0.z, acc[2]); acc[3] = fmaf(xv, a0.w, acc[3]);
            acc[4] = fmaf(xv, a1.x, acc[4]); acc[5] = fmaf(xv, a1.y, acc[5]);
            acc[6] = fmaf(xv, a1.z, acc[6]); acc[7] = fmaf(xv, a1.w, acc[7]);
        }
        float mkk = sm.maskS[s];
#pragma unroll
        for (int h = 0; h < 8; h++) sm.LG[h * 512 + s] = (mkk != 0.0f) ? acc[h] : -1e9f;
    }
    __syncthreads();

    // ---- Phase 4: softmax over s per head (64 threads per head) ----
    {
        int h = tid >> 6, u = tid & 63;
        float vals[8];
        float lm = -3.4e38f;
#pragma unroll
        for (int k2 = 0; k2 < 8; k2++) {
            vals[k2] = sm.LG[h * 512 + u + k2 * 64];
            lm = fmaxf(lm, vals[k2]);
        }
#pragma unroll
        for (int o = 16; o; o >>= 1) lm = fmaxf(lm, __shfl_xor_sync(0xffffffffu, lm, o));
        if (lane == 0) sm.wred[w] = lm;
        __syncthreads();
        lm = fmaxf(sm.wred[2 * h], sm.wred[2 * h + 1]);
        float ls = 0.f;
#pragma unroll
        for (int k2 = 0; k2 < 8; k2++) {
            vals[k2] = __expf(vals[k2] - lm);
            ls += vals[k2];
        }
#pragma unroll
        for (int o = 16; o; o >>= 1) ls += __shfl_xor_sync(0xffffffffu, ls, o);
        __syncthreads();
        if (lane == 0) sm.wred[w] = ls;
        __syncthreads();
        float inv = 1.0f / (sm.wred[2 * h] + sm.wred[2 * h + 1]);
#pragma unroll
        for (int k2 = 0; k2 < 8; k2++) sm.LG[h * 512 + u + k2 * 64] = vals[k2] * inv;
    }
    __syncthreads();

    // ---- Phase 5: y[h][j] = sum_s attn[h][s] * x[j][s], then og = y @ wv ----
    {
        int j = tid & 63, ch = tid >> 6;
        float acc[8] = {0, 0, 0, 0, 0, 0, 0, 0};
        const float* xr = &sm.xs[j * SP + ch * 64];
#pragma unroll 4
        for (int i = 0; i < 64; i++) {
            float xv = xr[i];
#pragma unroll
            for (int h = 0; h < 8; h++) acc[h] = fmaf(sm.LG[h * 512 + ch * 64 + i], xv, acc[h]);
        }
#pragma unroll
        for (int h = 0; h < 8; h++) sm.pbuf[ch * 512 + h * 64 + j] = acc[h];
    }
    __syncthreads();
    {
        float acc = 0.f;
#pragma unroll
        for (int ch = 0; ch < 8; ch++) acc += sm.pbuf[ch * 512 + tid];
        sm.ys[tid] = acc;
    }
    __syncthreads();
    if (tid < 64) {
        int h = tid >> 3;
        float acc = 0.f;
#pragma unroll
        for (int j = 0; j < 64; j++) acc = fmaf(sm.ys[h * 64 + j], wv[j * 64 + tid], acc);
        sm.og[tid] = acc;
    }
    __syncthreads();

    // ---- Phase 6: per-row gated output: out = (sigmoid(x@wg+bg)*og) @ wo + bo, masked ----
    {
        const float og0 = sm.og[2 * lane], og1 = sm.og[2 * lane + 1];
        const float bg0 = bg[2 * lane], bg1 = bg[2 * lane + 1];
        const float bo0 = bo[2 * lane], bo1 = bo[2 * lane + 1];
        float* trow0 = &sm.trow[w * 128];
        const float2* wg2 = reinterpret_cast<const float2*>(sm.wgs);
        const float2* wo2 = reinterpret_cast<const float2*>(sm.wos);
#pragma unroll 1
        for (int rp = 0; rp < 16; rp++) {
            int s0 = w * 32 + rp * 2;
            int s1 = s0 + 1;
            float a00 = 0, a01 = 0, a10 = 0, a11 = 0;
#pragma unroll 8
            for (int j = 0; j < 64; j++) {
                float x0 = sm.xs[j * SP + s0];
                float x1 = sm.xs[j * SP + s1];
                float2 wv2 = wg2[j * 32 + lane];
                a00 = fmaf(x0, wv2.x, a00); a01 = fmaf(x0, wv2.y, a01);
                a10 = fmaf(x1, wv2.x, a10); a11 = fmaf(x1, wv2.y, a11);
            }
            float t00 = og0 / (1.0f + __expf(-(a00 + bg0)));
            float t01 = og1 / (1.0f + __expf(-(a01 + bg1)));
            float t10 = og0 / (1.0f + __expf(-(a10 + bg0)));
            float t11 = og1 / (1.0f + __expf(-(a11 + bg1)));
            reinterpret_cast<float2*>(trow0)[lane]      = make_float2(t00, t01);
            reinterpret_cast<float2*>(trow0)[32 + lane] = make_float2(t10, t11);
            __syncwarp();
            float o00 = 0, o01 = 0, o10 = 0, o11 = 0;
#pragma unroll 8
            for (int hc = 0; hc < 64; hc++) {
                float th0 = trow0[hc];
                float th1 = trow0[64 + hc];
                float2 wv2 = wo2[hc * 32 + lane];
                o00 = fmaf(th0, wv2.x, o00); o01 = fmaf(th0, wv2.y, o01);
                o10 = fmaf(th1, wv2.x, o10); o11 = fmaf(th1, wv2.y, o11);
            }
            float mk0 = sm.maskS[s0], mk1 = sm.maskS[s1];
            *reinterpret_cast<float2*>(oBase + (size_t)s0 * rowStride + 2 * lane) =
                make_float2((o00 + bo0) * mk0, (o01 + bo1) * mk0);
            *reinterpret_cast<float2*>(oBase + (size_t)s1 * rowStride + 2 * lane) =
                make_float2((o10 + bo0) * mk1, (o11 + bo1) * mk1);
            __syncwarp();
        }
    }
}

extern "C" void kernel_launch(void* const* d_in, const int* in_sizes, int n_in,
                              void* d_out, int out_size)
{
    (void)in_sizes; (void)n_in; (void)out_size;
    const float* m    = (const float*)d_in[0];
    const float* mask = (const float*)d_in[1];
    const float* lnw  = (const float*)d_in[2];
    const float* lnb  = (const float*)d_in[3];
    const float* wq   = (const float*)d_in[4];
    const float* wk   = (const float*)d_in[5];
    const float* wv   = (const float*)d_in[6];
    const float* wg   = (const float*)d_in[7];
    const float* bg   = (const float*)d_in[8];
    const float* wo   = (const float*)d_in[9];
    const float* bo   = (const float*)d_in[10];
    float* out = (float*)d_out;

    cudaFuncSetAttribute(msa_col_global_attn,
                         cudaFuncAttributeMaxDynamicSharedMemorySize,
                         (int)sizeof(SMem));
    msa_col_global_attn<<<Bb * Ll, NTHREADS, sizeof(SMem)>>>(
        m, mask, lnw, lnb, wq, wk, wv, wg, bg, wo, bo, out);
}

// round 2
// speedup vs baseline: 1.4275x; 1.4275x over previous
#include <cuda_runtime.h>

#define NTHREADS 512
#define SPt 516   // xs stride: mult of 4 (16B-aligned float4), gcd(516,32)=4

namespace {
constexpr int Bb = 2, Ss = 512, Ll = 384, CMc = 64;

struct SMem {
    float xs[64 * SPt];    // post-LN x, transposed [c][s]
    float wgs[4096];
    float wos[4096];
    float maskS[512];
    union {
        struct { float LG[4096]; float pbuf[4096]; } a;  // logits/attn + partials
        float trow[8192];                                 // phase-6 per-warp t buffer
    } u;
    float amt[512];        // a transposed [j][h]
    float qin[64];
    float qsm[64];
    float ys[512];
    float og[64];
    float wred[16];
    float invDenom;
};
}  // namespace

__device__ __forceinline__ unsigned long long splat2(float v) {
    unsigned long long r;
    asm("mov.b64 %0, {%1, %1};" : "=l"(r) : "f"(v));
    return r;
}
__device__ __forceinline__ void fma2(unsigned long long& d, unsigned long long a,
                                     unsigned long long b) {
    asm("fma.rn.f32x2 %0, %1, %2, %0;" : "+l"(d) : "l"(a), "l"(b));
}
__device__ __forceinline__ float2 unpk(unsigned long long v) {
    float2 f;
    asm("mov.b64 {%0, %1}, %2;" : "=f"(f.x), "=f"(f.y) : "l"(v));
    return f;
}
__device__ __forceinline__ float sgm(float x) { return 1.0f / (1.0f + __expf(-x)); }

__global__ void __launch_bounds__(NTHREADS, 1)
msa_col_global_attn(const float* __restrict__ m, const float* __restrict__ msa_mask,
                    const float* __restrict__ lnw, const float* __restrict__ lnb,
                    const float* __restrict__ wq, const float* __restrict__ wk,
                    const float* __restrict__ wv, const float* __restrict__ wg,
                    const float* __restrict__ bg, const float* __restrict__ wo,
                    const float* __restrict__ bo, float* __restrict__ out)
{
    extern __shared__ char smraw[];
    SMem& sm = *reinterpret_cast<SMem*>(smraw);
    const int tid = threadIdx.x;
    const int w = tid >> 5, lane = tid & 31;
    const int b = blockIdx.x / Ll, l = blockIdx.x - b * Ll;
    const size_t rowStride = (size_t)Ll * CMc;
    const float* mBase = m + ((size_t)b * Ss * Ll + l) * CMc;
    float* oBase = out + ((size_t)b * Ss * Ll + l) * CMc;

    // ---- Phase 0: mask load + denom partial, weight staging ----
    float mk = msa_mask[((size_t)b * Ss + tid) * Ll + l];
    sm.maskS[tid] = mk;
    float msum = mk;
#pragma unroll
    for (int o = 16; o; o >>= 1) msum += __shfl_xor_sync(0xffffffffu, msum, o);
    if (lane == 0) sm.wred[w] = msum;

    for (int idx = tid; idx < 2048; idx += NTHREADS) {
        reinterpret_cast<float2*>(sm.wgs)[idx] = reinterpret_cast<const float2*>(wg)[idx];
        reinterpret_cast<float2*>(sm.wos)[idx] = reinterpret_cast<const float2*>(wo)[idx];
    }
    __syncthreads();
    if (tid == 0) {
        float s = 0.f;
#pragma unroll
        for (int i = 0; i < 16; i++) s += sm.wred[i];
        sm.invDenom = 1.0f / fmaxf(s, 1.0f);
    }

    // ---- Phase 1: load m column + LayerNorm -> xs[c][s] (lane owns c=lane, c=lane+32) ----
    {
        const float lwA = lnw[lane], lwB = lnw[lane + 32];
        const float lbA = lnb[lane], lbB = lnb[lane + 32];
#pragma unroll 1
        for (int rb = 0; rb < 4; rb++) {
            float a0[8], a1[8];
#pragma unroll
            for (int r = 0; r < 8; r++) {
                int s = w * 32 + rb * 8 + r;
                const float* mp = mBase + (size_t)s * rowStride;
                a0[r] = mp[lane];
                a1[r] = mp[lane + 32];
            }
#pragma unroll
            for (int r = 0; r < 8; r++) {
                int s = w * 32 + rb * 8 + r;
                float su = a0[r] + a1[r];
                float sq = fmaf(a0[r], a0[r], a1[r] * a1[r]);
#pragma unroll
                for (int o = 16; o; o >>= 1) {
                    su += __shfl_xor_sync(0xffffffffu, su, o);
                    sq += __shfl_xor_sync(0xffffffffu, sq, o);
                }
                float mu = su * (1.0f / 64.0f);
                float var = sq * (1.0f / 64.0f) - mu * mu;
                float rs = rsqrtf(var + 1e-5f);
                sm.xs[lane * SPt + s]        = (a0[r] - mu) * rs * lwA + lbA;
                sm.xs[(lane + 32) * SPt + s] = (a1[r] - mu) * rs * lwB + lbB;
            }
        }
    }
    __syncthreads();

    // ---- Phase 2: masked column sum -> q_input -> q -> a[j][h] ----
    {
        int j = tid & 63, ch = tid >> 6;
        const float* xr = &sm.xs[j * SPt + ch * 64];
        const float* mr = &sm.maskS[ch * 64];
        float acc = 0.f;
#pragma unroll
        for (int ib = 0; ib < 16; ib++) {
            float4 xq = *reinterpret_cast<const float4*>(xr + ib * 4);
            float4 mq = *reinterpret_cast<const float4*>(mr + ib * 4);
            acc = fmaf(xq.x, mq.x, acc);
            acc = fmaf(xq.y, mq.y, acc);
            acc = fmaf(xq.z, mq.z, acc);
            acc = fmaf(xq.w, mq.w, acc);
        }
        sm.u.a.pbuf[ch * 512 + j] = acc;
    }
    __syncthreads();
    if (tid < 64) {
        float acc = 0.f;
#pragma unroll
        for (int ch = 0; ch < 8; ch++) acc += sm.u.a.pbuf[ch * 512 + tid];
        sm.qin[tid] = acc * sm.invDenom;
    }
    __syncthreads();
    if (tid < 64) {
        float acc = 0.f;
#pragma unroll
        for (int j = 0; j < 64; j++) acc = fmaf(sm.qin[j], wq[j * 64 + tid], acc);
        sm.qsm[tid] = acc;
    }
    __syncthreads();
    {
        int h = tid >> 6, j = tid & 63;
        float acc = 0.f;
#pragma unroll
        for (int c = 0; c < 8; c++) acc = fmaf(sm.qsm[h * 8 + c], wk[j * 64 + h * 8 + c], acc);
        sm.amt[j * 8 + h] = acc * 0.35355339059327373f;  // 1/sqrt(C)
    }
    __syncthreads();

    // ---- Phase 3: logits[h][s] = x[s]·a[h], masked ----
    {
        int s = tid;
        float acc[8] = {0, 0, 0, 0, 0, 0, 0, 0};
#pragma unroll 8
        for (int j = 0; j < 64; j++) {
            float xv = sm.xs[j * SPt + s];
            const float4* ap = reinterpret_cast<const float4*>(&sm.amt[j * 8]);
            float4 q0 = ap[0], q1 = ap[1];
            acc[0] = fmaf(xv, q0.x, acc[0]); acc[1] = fmaf(xv, q0.y, acc[1]);
            acc[2] = fmaf(xv, q0.z, acc[2]); acc[3] = fmaf(xv, q0.w, acc[3]);
            acc[4] = fmaf(xv, q1.x, acc[4]); acc[5] = fmaf(xv, q1.y, acc[5]);
            acc[6] = fmaf(xv, q1.z, acc[6]); acc[7] = fmaf(xv, q1.w, acc[7]);
        }
        float mkk = sm.maskS[s];
#pragma unroll
        for (int h = 0; h < 8; h++) sm.u.a.LG[h * 512 + s] = (mkk != 0.0f) ? acc[h] : -1e9f;
    }
    __syncthreads();

    // ---- Phase 4: softmax over s per head ----
    {
        int h = tid >> 6, uu = tid & 63;
        float vals[8];
        float lm = -3.4e38f;
#pragma unroll
        for (int k2 = 0; k2 < 8; k2++) {
            vals[k2] = sm.u.a.LG[h * 512 + uu + k2 * 64];
            lm = fmaxf(lm, vals[k2]);
        }
#pragma unroll
        for (int o = 16; o; o >>= 1) lm = fmaxf(lm, __shfl_xor_sync(0xffffffffu, lm, o));
        if (lane == 0) sm.wred[w] = lm;
        __syncthreads();
        lm = fmaxf(sm.wred[2 * h], sm.wred[2 * h + 1]);
        float ls = 0.f;
#pragma unroll
        for (int k2 = 0; k2 < 8; k2++) {
            vals[k2] = __expf(vals[k2] - lm);
            ls += vals[k2];
        }
#pragma unroll
        for (int o = 16; o; o >>= 1) ls += __shfl_xor_sync(0xffffffffu, ls, o);
        __syncthreads();
        if (lane == 0) sm.wred[w] = ls;
        __syncthreads();
        float inv = 1.0f / (sm.wred[2 * h] + sm.wred[2 * h + 1]);
#pragma unroll
        for (int k2 = 0; k2 < 8; k2++) sm.u.a.LG[h * 512 + uu + k2 * 64] = vals[k2] * inv;
    }
    __syncthreads();

    // ---- Phase 5: y[h][j] = sum_s attn[h][s]*x[j][s], then og = y @ wv ----
    {
        int j = tid & 63, ch = tid >> 6;
        float acc[8] = {0, 0, 0, 0, 0, 0, 0, 0};
        const float* xr = &sm.xs[j * SPt + ch * 64];
#pragma unroll 2
        for (int ib = 0; ib < 16; ib++) {
            float4 xq = *reinterpret_cast<const float4*>(xr + ib * 4);
#pragma unroll
            for (int h = 0; h < 8; h++) {
                float4 aq = *reinterpret_cast<const float4*>(&sm.u.a.LG[h * 512 + ch * 64 + ib * 4]);
                acc[h] = fmaf(aq.x, xq.x, acc[h]);
                acc[h] = fmaf(aq.y, xq.y, acc[h]);
                acc[h] = fmaf(aq.z, xq.z, acc[h]);
                acc[h] = fmaf(aq.w, xq.w, acc[h]);
            }
        }
#pragma unroll
        for (int h = 0; h < 8; h++) sm.u.a.pbuf[ch * 512 + h * 64 + j] = acc[h];
    }
    __syncthreads();
    {
        float acc = 0.f;
#pragma unroll
        for (int ch = 0; ch < 8; ch++) acc += sm.u.a.pbuf[ch * 512 + tid];
        sm.ys[tid] = acc;
    }
    __syncthreads();
    if (tid < 64) {
        int h = tid >> 3;
        float acc = 0.f;
#pragma unroll
        for (int j = 0; j < 64; j++) acc = fmaf(sm.ys[h * 64 + j], wv[j * 64 + tid], acc);
        sm.og[tid] = acc;
    }
    __syncthreads();

    // ---- Phase 6: out = (sigmoid(x@wg+bg)*og) @ wo + bo, masked. 8-row blocks, f32x2 ----
    {
        const int c0 = 2 * lane;
        const float og0 = sm.og[c0], og1 = sm.og[c0 + 1];
        const float bg0 = bg[c0], bg1 = bg[c0 + 1];
        const float bo0 = bo[c0], bo1 = bo[c0 + 1];
        float* trw = &sm.u.trow[w * 512];
        const float2* wg2 = reinterpret_cast<const float2*>(sm.wgs);
        const float2* wo2 = reinterpret_cast<const float2*>(sm.wos);
#pragma unroll 1
        for (int rp = 0; rp < 4; rp++) {
            const int s0 = w * 32 + rp * 8;
            unsigned long long A[4][2];
#pragma unroll
            for (int p = 0; p < 4; p++) { A[p][0] = 0ull; A[p][1] = 0ull; }
#pragma unroll 4
            for (int j = 0; j < 64; j++) {
                const ulonglong2* xp = reinterpret_cast<const ulonglong2*>(&sm.xs[j * SPt + s0]);
                ulonglong2 xa = xp[0];
                ulonglong2 xb = xp[1];
                float2 wcp = wg2[j * 32 + lane];
                unsigned long long w0 = splat2(wcp.x), w1 = splat2(wcp.y);
                fma2(A[0][0], xa.x, w0); fma2(A[0][1], xa.x, w1);
                fma2(A[1][0], xa.y, w0); fma2(A[1][1], xa.y, w1);
                fma2(A[2][0], xb.x, w0); fma2(A[2][1], xb.x, w1);
                fma2(A[3][0], xb.y, w0); fma2(A[3][1], xb.y, w1);
            }
            // gate: t[row][col] = og[col]*sigmoid(a+bg[col]); stage as trow[hc][r]
            float t0[8], t1[8];
#pragma unroll
            for (int p = 0; p < 4; p++) {
                float2 ac0 = unpk(A[p][0]);
                float2 ac1 = unpk(A[p][1]);
                t0[2 * p]     = og0 * sgm(ac0.x + bg0);
                t0[2 * p + 1] = og0 * sgm(ac0.y + bg0);
                t1[2 * p]     = og1 * sgm(ac1.x + bg1);
                t1[2 * p + 1] = og1 * sgm(ac1.y + bg1);
            }
            *reinterpret_cast<float4*>(&trw[c0 * 8])       = make_float4(t0[0], t0[1], t0[2], t0[3]);
            *reinterpret_cast<float4*>(&trw[c0 * 8 + 4])   = make_float4(t0[4], t0[5], t0[6], t0[7]);
            *reinterpret_cast<float4*>(&trw[(c0 + 1) * 8])     = make_float4(t1[0], t1[1], t1[2], t1[3]);
            *reinterpret_cast<float4*>(&trw[(c0 + 1) * 8 + 4]) = make_float4(t1[4], t1[5], t1[6], t1[7]);
            __syncwarp();
            unsigned long long O[4][2];
#pragma unroll
            for (int p = 0; p < 4; p++) { O[p][0] = 0ull; O[p][1] = 0ull; }
#pragma unroll 4
            for (int hc = 0; hc < 64; hc++) {
                const ulonglong2* tp = reinterpret_cast<const ulonglong2*>(&trw[hc * 8]);
                ulonglong2 ta = tp[0];
                ulonglong2 tb = tp[1];
                float2 wop = wo2[hc * 32 + lane];
                unsigned long long w0 = splat2(wop.x), w1 = splat2(wop.y);
                fma2(O[0][0], ta.x, w0); fma2(O[0][1], ta.x, w1);
                fma2(O[1][0], ta.y, w0); fma2(O[1][1], ta.y, w1);
                fma2(O[2][0], tb.x, w0); fma2(O[2][1], tb.x, w1);
                fma2(O[3][0], tb.y, w0); fma2(O[3][1], tb.y, w1);
            }
#pragma unroll
            for (int p = 0; p < 4; p++) {
                float2 oc0 = unpk(O[p][0]);
                float2 oc1 = unpk(O[p][1]);
                int sA = s0 + 2 * p, sB = sA + 1;
                float mkA = sm.maskS[sA], mkB = sm.maskS[sB];
                *reinterpret_cast<float2*>(oBase + (size_t)sA * rowStride + c0) =
                    make_float2((oc0.x + bo0) * mkA, (oc1.x + bo1) * mkA);
                *reinterpret_cast<float2*>(oBase + (size_t)sB * rowStride + c0) =
                    make_float2((oc0.y + bo0) * mkB, (oc1.y + bo1) * mkB);
            }
            __syncwarp();
        }
    }
}

extern "C" void kernel_launch(void* const* d_in, const int* in_sizes, int n_in,
                              void* d_out, int out_size)
{
    (void)in_sizes; (void)n_in; (void)out_size;
    const float* m    = (const float*)d_in[0];
    const float* mask = (const float*)d_in[1];
    const float* lnw  = (const float*)d_in[2];
    const float* lnb  = (const float*)d_in[3];
    const float* wq   = (const float*)d_in[4];
    const float* wk   = (const float*)d_in[5];
    const float* wv   = (const float*)d_in[6];
    const float* wg   = (const float*)d_in[7];
    const float* bg   = (const float*)d_in[8];
    const float* wo   = (const float*)d_in[9];
    const float* bo   = (const float*)d_in[10];
    float* out = (float*)d_out;

    cudaFuncSetAttribute(msa_col_global_attn,
                         cudaFuncAttributeMaxDynamicSharedMemorySize,
                         (int)sizeof(SMem));
    msa_col_global_attn<<<Bb * Ll, NTHREADS, sizeof(SMem)>>>(
        m, mask, lnw, lnb, wq, wk, wv, wg, bg, wo, bo, out);
}

// round 4
// speedup vs baseline: 1.5957x; 1.1178x over previous
#include <cuda_runtime.h>
#include <cuda_fp16.h>
#include <cstdint>
#include <cstddef>

#define NT 256
#define SP2 260   // xs stride: mult of 4 for float4, breaks store-bank alignment a bit

namespace {
constexpr int Bb = 2, Ss = 512, Ll = 384, CMc = 64;
constexpr int Sh = 256;   // rows per CTA (cluster of 2 covers S=512)

struct SMem {
    float xs[64 * SP2];        // post-LN x, transposed [c][s_local]   66,560B
    __half2 wgh[2048];         // wg fp16, [j][colpair]                 8,192B
    __half2 woh[2048];         // wo fp16                               8,192B
    union {
        struct { float LG[8 * Sh]; float pbuf[4 * 512]; } a;  // 16,384B
        float trow[8 * 512];   // phase-6 per-warp t buffer
    } u;
    float maskS[Sh];           // local mask
    float amt[512];            // a transposed [j][h]
    float ys[512];             // scaled local y
    float yP[512];             // peer y mailbox
    float qin[64];
    float qinP[64];            // peer qin mailbox
    float qsm[64];
    float og[64];
    float red[8];
    float fH[8];
    float hmsP[16];            // peer head (max, sum) mailbox
    float mloc;                // local mask sum
    float msP;                 // peer mask sum mailbox
};
}  // namespace

__device__ __forceinline__ unsigned long long splat2(float v) {
    unsigned long long r;
    asm("mov.b64 %0, {%1, %1};" : "=l"(r) : "f"(v));
    return r;
}
__device__ __forceinline__ void fma2(unsigned long long& d, unsigned long long a,
                                     unsigned long long b) {
    asm("fma.rn.f32x2 %0, %1, %2, %0;" : "+l"(d) : "l"(a), "l"(b));
}
__device__ __forceinline__ float2 unpk(unsigned long long v) {
    float2 f;
    asm("mov.b64 {%0, %1}, %2;" : "=f"(f.x), "=f"(f.y) : "l"(v));
    return f;
}
__device__ __forceinline__ float sgm(float x) { return 1.0f / (1.0f + __expf(-x)); }

__device__ __forceinline__ uint32_t s2u(const void* p) {
    uint32_t a;
    asm("{ .reg .u64 t; cvta.to.shared.u64 t, %1; cvt.u32.u64 %0, t; }" : "=r"(a) : "l"(p));
    return a;
}
__device__ __forceinline__ void st_peer(uint32_t laddr, uint32_t peer, float v) {
    uint32_t ra;
    asm volatile("mapa.shared::cluster.u32 %0, %1, %2;" : "=r"(ra) : "r"(laddr), "r"(peer));
    asm volatile("st.shared::cluster.f32 [%0], %1;" :: "r"(ra), "f"(v) : "memory");
}
__device__ __forceinline__ void cluster_sync() {
    asm volatile("barrier.cluster.arrive.aligned;" ::: "memory");
    asm volatile("barrier.cluster.wait.aligned;" ::: "memory");
}
__device__ __forceinline__ uint32_t ctarank() {
    uint32_t r;
    asm("mov.u32 %0, %%cluster_ctarank;" : "=r"(r));
    return r;
}

__global__ void __launch_bounds__(NT, 1) __cluster_dims__(2, 1, 1)
msa_col_global_attn(const float* __restrict__ m, const float* __restrict__ msa_mask,
                    const float* __restrict__ lnw, const float* __restrict__ lnb,
                    const float* __restrict__ wq, const float* __restrict__ wk,
                    const float* __restrict__ wv, const float* __restrict__ wg,
                    const float* __restrict__ bg, const float* __restrict__ wo,
                    const float* __restrict__ bo, float* __restrict__ out)
{
    extern __shared__ char smraw[];
    SMem& sm = *reinterpret_cast<SMem*>(smraw);
    const int tid = threadIdx.x;
    const int w = tid >> 5, lane = tid & 31;
    const uint32_t rank = ctarank();
    const uint32_t peer = rank ^ 1u;
    const int col = blockIdx.x >> 1;
    const int b = col / Ll, l = col - b * Ll;
    const int sBase = rank * Sh;  // global row offset of this CTA's half
    const size_t rowStride = (size_t)Ll * CMc;
    const float* mBase = m + ((size_t)b * Ss * Ll + l) * CMc;
    float* oBase = out + ((size_t)b * Ss * Ll + l) * CMc;

    // ---- Phase 0: local mask + partial sum; weight staging (fp32->fp16) ----
    float mk = msa_mask[((size_t)b * Ss + sBase + tid) * Ll + l];
    sm.maskS[tid] = mk;
    float msum = mk;
#pragma unroll
    for (int o = 16; o; o >>= 1) msum += __shfl_xor_sync(0xffffffffu, msum, o);
    if (lane == 0) sm.red[w] = msum;

    for (int idx = tid; idx < 2048; idx += NT) {
        float2 g2 = __ldg(&reinterpret_cast<const float2*>(wg)[idx]);
        sm.wgh[idx] = __float22half2_rn(g2);
        float2 o2 = __ldg(&reinterpret_cast<const float2*>(wo)[idx]);
        sm.woh[idx] = __float22half2_rn(o2);
    }

    // ---- Phase 1: load m rows + LayerNorm -> xs[c][s_local] ----
    {
        const float lwA = lnw[lane], lwB = lnw[lane + 32];
        const float lbA = lnb[lane], lbB = lnb[lane + 32];
#pragma unroll 1
        for (int rb = 0; rb < 4; rb++) {
            float a0[8], a1[8];
#pragma unroll
            for (int r = 0; r < 8; r++) {
                int s = w * 32 + rb * 8 + r;
                const float* mp = mBase + (size_t)(sBase + s) * rowStride;
                a0[r] = mp[lane];
                a1[r] = mp[lane + 32];
            }
#pragma unroll
            for (int r = 0; r < 8; r++) {
                int s = w * 32 + rb * 8 + r;
                float su = a0[r] + a1[r];
                float sq = fmaf(a0[r], a0[r], a1[r] * a1[r]);
#pragma unroll
                for (int o = 16; o; o >>= 1) {
                    su += __shfl_xor_sync(0xffffffffu, su, o);
                    sq += __shfl_xor_sync(0xffffffffu, sq, o);
                }
                float mu = su * (1.0f / 64.0f);
                float var = sq * (1.0f / 64.0f) - mu * mu;
                float rs = rsqrtf(var + 1e-5f);
                sm.xs[lane * SP2 + s]        = (a0[r] - mu) * rs * lwA + lbA;
                sm.xs[(lane + 32) * SP2 + s] = (a1[r] - mu) * rs * lwB + lbB;
            }
        }
    }
    __syncthreads();
    if (tid == 0) {
        float s = 0.f;
#pragma unroll
        for (int i = 0; i < 8; i++) s += sm.red[i];
        sm.mloc = s;
    }

    // ---- Phase 2: local masked column sum -> qin partial; exchange ----
    {
        int j = tid & 63, ch = tid >> 6;
        const float* xr = &sm.xs[j * SP2 + ch * 64];
        const float* mr = &sm.maskS[ch * 64];
        float acc = 0.f;
#pragma unroll
        for (int ib = 0; ib < 16; ib++) {
            float4 xq = *reinterpret_cast<const float4*>(xr + ib * 4);
            float4 mq = *reinterpret_cast<const float4*>(mr + ib * 4);
            acc = fmaf(xq.x, mq.x, acc);
            acc = fmaf(xq.y, mq.y, acc);
            acc = fmaf(xq.z, mq.z, acc);
            acc = fmaf(xq.w, mq.w, acc);
        }
        sm.u.a.pbuf[tid] = acc;  // [ch*64 + j]
    }
    __syncthreads();
    if (tid < 64) {
        float acc = sm.u.a.pbuf[tid] + sm.u.a.pbuf[64 + tid] +
                    sm.u.a.pbuf[128 + tid] + sm.u.a.pbuf[192 + tid];
        sm.qin[tid] = acc;
        st_peer(s2u(&sm.qinP[tid]), peer, acc);
    }
    if (tid == 0) st_peer(s2u(&sm.msP), peer, sm.mloc);
    cluster_sync();  // #1

    // ---- combine qin, compute q then a[j][h] ----
    if (tid < 64) {
        float inv = 1.0f / fmaxf(sm.mloc + sm.msP, 1.0f);
        sm.qin[tid] = (sm.qin[tid] + sm.qinP[tid]) * inv;
    }
    __syncthreads();
    if (tid < 64) {
        float acc = 0.f;
#pragma unroll
        for (int j = 0; j < 64; j++) acc = fmaf(sm.qin[j], __ldg(&wq[j * 64 + tid]), acc);
        sm.qsm[tid] = acc;
    }
    __syncthreads();
    {
#pragma unroll
        for (int t2 = 0; t2 < 2; t2++) {
            int idx = 2 * tid + t2;
            int j = idx >> 3, h = idx & 7;
            float acc = 0.f;
#pragma unroll
            for (int c = 0; c < 8; c++)
                acc = fmaf(sm.qsm[h * 8 + c], __ldg(&wk[j * 64 + h * 8 + c]), acc);
            sm.amt[j * 8 + h] = acc * 0.35355339059327373f;  // 1/sqrt(C)
        }
    }
    __syncthreads();

    // ---- Phase 3: logits[h][s_local] = x[s]·a[h], masked ----
    {
        int s = tid;
        float acc[8] = {0, 0, 0, 0, 0, 0, 0, 0};
#pragma unroll 8
        for (int j = 0; j < 64; j++) {
            float xv = sm.xs[j * SP2 + s];
            const float4* ap = reinterpret_cast<const float4*>(&sm.amt[j * 8]);
            float4 q0 = ap[0], q1 = ap[1];
            acc[0] = fmaf(xv, q0.x, acc[0]); acc[1] = fmaf(xv, q0.y, acc[1]);
            acc[2] = fmaf(xv, q0.z, acc[2]); acc[3] = fmaf(xv, q0.w, acc[3]);
            acc[4] = fmaf(xv, q1.x, acc[4]); acc[5] = fmaf(xv, q1.y, acc[5]);
            acc[6] = fmaf(xv, q1.z, acc[6]); acc[7] = fmaf(xv, q1.w, acc[7]);
        }
        float mkk = sm.maskS[s];
#pragma unroll
        for (int h = 0; h < 8; h++) sm.u.a.LG[h * Sh + s] = (mkk != 0.0f) ? acc[h] : -1e9f;
    }
    __syncthreads();

    // ---- Phase 4: per-head local max/sumexp (warp w == head w); exchange ----
    float lmKeep = 0.f, lsKeep = 0.f;
    {
        int head = w;
        float vals[8];
        float lm = -3.4e38f;
#pragma unroll
        for (int k2 = 0; k2 < 8; k2++) {
            vals[k2] = sm.u.a.LG[head * Sh + lane + k2 * 32];
            lm = fmaxf(lm, vals[k2]);
        }
#pragma unroll
        for (int o = 16; o; o >>= 1) lm = fmaxf(lm, __shfl_xor_sync(0xffffffffu, lm, o));
        float ls = 0.f;
#pragma unroll
        for (int k2 = 0; k2 < 8; k2++) {
            vals[k2] = __expf(vals[k2] - lm);
            ls += vals[k2];
        }
#pragma unroll
        for (int k2 = 0; k2 < 8; k2++) sm.u.a.LG[head * Sh + lane + k2 * 32] = vals[k2];
#pragma unroll
        for (int o = 16; o; o >>= 1) ls += __shfl_xor_sync(0xffffffffu, ls, o);
        if (lane == 0) {
            st_peer(s2u(&sm.hmsP[head]), peer, lm);
            st_peer(s2u(&sm.hmsP[8 + head]), peer, ls);
        }
        lmKeep = lm; lsKeep = ls;
    }
    cluster_sync();  // #2
    if (lane == 0) {
        float mP = sm.hmsP[w], sP = sm.hmsP[8 + w];
        float M = fmaxf(lmKeep, mP);
        float D = lsKeep * __expf(lmKeep - M) + sP * __expf(mP - M);
        sm.fH[w] = __expf(lmKeep - M) / D;
    }
    __syncthreads();

    // ---- Phase 5: local y partial; scale by fH; exchange; og = y @ wv ----
    {
        int j = tid & 63, ch = tid >> 6;
        float acc[8] = {0, 0, 0, 0, 0, 0, 0, 0};
        const float* xr = &sm.xs[j * SP2 + ch * 64];
#pragma unroll 2
        for (int ib = 0; ib < 16; ib++) {
            float4 xq = *reinterpret_cast<const float4*>(xr + ib * 4);
#pragma unroll
            for (int h = 0; h < 8; h++) {
                float4 aq = *reinterpret_cast<const float4*>(&sm.u.a.LG[h * Sh + ch * 64 + ib * 4]);
                acc[h] = fmaf(aq.x, xq.x, acc[h]);
                acc[h] = fmaf(aq.y, xq.y, acc[h]);
                acc[h] = fmaf(aq.z, xq.z, acc[h]);
                acc[h] = fmaf(aq.w, xq.w, acc[h]);
            }
        }
#pragma unroll
        for (int h = 0; h < 8; h++) sm.u.a.pbuf[ch * 512 + h * 64 + j] = acc[h];
    }
    __syncthreads();
    {
#pragma unroll
        for (int t2 = 0; t2 < 2; t2++) {
            int idx = tid + t2 * 256;
            float v = sm.u.a.pbuf[idx] + sm.u.a.pbuf[512 + idx] +
                      sm.u.a.pbuf[1024 + idx] + sm.u.a.pbuf[1536 + idx];
            v *= sm.fH[idx >> 6];
            sm.ys[idx] = v;
            st_peer(s2u(&sm.yP[idx]), peer, v);
        }
    }
    cluster_sync();  // #3
    if (tid < 64) {
        int h = tid >> 3;
        float acc = 0.f;
#pragma unroll
        for (int j = 0; j < 64; j++)
            acc = fmaf(sm.ys[h * 64 + j] + sm.yP[h * 64 + j], __ldg(&wv[j * 64 + tid]), acc);
        sm.og[tid] = acc;
    }
    __syncthreads();

    // ---- Phase 6: out = (sigmoid(x@wg+bg)*og) @ wo + bo, masked. 8-row f32x2 ----
    {
        const int c0 = 2 * lane;
        const float og0 = sm.og[c0], og1 = sm.og[c0 + 1];
        const float bg0 = bg[c0], bg1 = bg[c0 + 1];
        const float bo0 = bo[c0], bo1 = bo[c0 + 1];
        float* trw = &sm.u.trow[w * 512];
#pragma unroll 1
        for (int rp = 0; rp < 4; rp++) {
            const int s0 = w * 32 + rp * 8;
            unsigned long long A[4][2];
#pragma unroll
            for (int p = 0; p < 4; p++) { A[p][0] = 0ull; A[p][1] = 0ull; }
#pragma unroll 4
            for (int j = 0; j < 64; j++) {
                const ulonglong2* xp = reinterpret_cast<const ulonglong2*>(&sm.xs[j * SP2 + s0]);
                ulonglong2 xa = xp[0];
                ulonglong2 xb = xp[1];
                float2 wcp = __half22float2(sm.wgh[j * 32 + lane]);
                unsigned long long w0 = splat2(wcp.x), w1 = splat2(wcp.y);
                fma2(A[0][0], xa.x, w0); fma2(A[0][1], xa.x, w1);
                fma2(A[1][0], xa.y, w0); fma2(A[1][1], xa.y, w1);
                fma2(A[2][0], xb.x, w0); fma2(A[2][1], xb.x, w1);
                fma2(A[3][0], xb.y, w0); fma2(A[3][1], xb.y, w1);
            }
            float t0[8], t1[8];
#pragma unroll
            for (int p = 0; p < 4; p++) {
                float2 ac0 = unpk(A[p][0]);
                float2 ac1 = unpk(A[p][1]);
                t0[2 * p]     = og0 * sgm(ac0.x + bg0);
                t0[2 * p + 1] = og0 * sgm(ac0.y + bg0);
                t1[2 * p]     = og1 * sgm(ac1.x + bg1);
                t1[2 * p + 1] = og1 * sgm(ac1.y + bg1);
            }
            *reinterpret_cast<float4*>(&trw[c0 * 8])       = make_float4(t0[0], t0[1], t0[2], t0[3]);
            *reinterpret_cast<float4*>(&trw[c0 * 8 + 4])   = make_float4(t0[4], t0[5], t0[6], t0[7]);
            *reinterpret_cast<float4*>(&trw[(c0 + 1) * 8])     = make_float4(t1[0], t1[1], t1[2], t1[3]);
            *reinterpret_cast<float4*>(&trw[(c0 + 1) * 8 + 4]) = make_float4(t1[4], t1[5], t1[6], t1[7]);
            __syncwarp();
            unsigned long long O[4][2];
#pragma unroll
            for (int p = 0; p < 4; p++) { O[p][0] = 0ull; O[p][1] = 0ull; }
#pragma unroll 4
            for (int hc = 0; hc < 64; hc++) {
                const ulonglong2* tp = reinterpret_cast<const ulonglong2*>(&trw[hc * 8]);
                ulonglong2 ta = tp[0];
                ulonglong2 tb = tp[1];
                float2 wop = __half22float2(sm.woh[hc * 32 + lane]);
                unsigned long long w0 = splat2(wop.x), w1 = splat2(wop.y);
                fma2(O[0][0], ta.x, w0); fma2(O[0][1], ta.x, w1);
                fma2(O[1][0], ta.y, w0); fma2(O[1][1], ta.y, w1);
                fma2(O[2][0], tb.x, w0); fma2(O[2][1], tb.x, w1);
                fma2(O[3][0], tb.y, w0); fma2(O[3][1], tb.y, w1);
            }
#pragma unroll
            for (int p = 0; p < 4; p++) {
                float2 oc0 = unpk(O[p][0]);
                float2 oc1 = unpk(O[p][1]);
                int sA = s0 + 2 * p, sB = sA + 1;
                float mkA = sm.maskS[sA], mkB = sm.maskS[sB];
                *reinterpret_cast<float2*>(oBase + (size_t)(sBase + sA) * rowStride + c0) =
                    make_float2((oc0.x + bo0) * mkA, (oc1.x + bo1) * mkA);
                *reinterpret_cast<float2*>(oBase + (size_t)(sBase + sB) * rowStride + c0) =
                    make_float2((oc0.y + bo0) * mkB, (oc1.y + bo1) * mkB);
            }
            __syncwarp();
        }
    }
}

extern "C" void kernel_launch(void* const* d_in, const int* in_sizes, int n_in,
                              void* d_out, int out_size)
{
    (void)in_sizes; (void)n_in; (void)out_size;
    const float* m    = (const float*)d_in[0];
    const float* mask = (const float*)d_in[1];
    const float* lnw  = (const float*)d_in[2];
    const float* lnb  = (const float*)d_in[3];
    const float* wq   = (const float*)d_in[4];
    const float* wk   = (const float*)d_in[5];
    const float* wv   = (const float*)d_in[6];
    const float* wg   = (const float*)d_in[7];
    const float* bg   = (const float*)d_in[8];
    const float* wo   = (const float*)d_in[9];
    const float* bo   = (const float*)d_in[10];
    float* out = (float*)d_out;

    cudaFuncSetAttribute(msa_col_global_attn,
                         cudaFuncAttributeMaxDynamicSharedMemorySize,
                         (int)sizeof(SMem));
    msa_col_global_attn<<<Bb * Ll * 2, NT, sizeof(SMem)>>>(
        m, mask, lnw, lnb, wq, wk, wv, wg, bg, wo, bo, out);
}